// round 1
// baseline (speedup 1.0000x reference)
#include <cuda_runtime.h>
#include <math.h>

#define BQ 2
#define LQ 5000
#define CIN 256
#define DLOI 128
#define NPTS0 32
#define NPTS1 8
#define HH 256
#define HALF 64
#define HW (HH*HH)
#define EPSBN 1e-5f

// ---------------- scratch (device globals; no allocation allowed) ----------------
__device__ float g_x[BQ * HW * DLOI];          // fc1 output, NHWC  (64 MB)
__device__ float g_wfc1T[CIN * DLOI];          // [k][o]
__device__ float g_c1wT[DLOI * HALF];          // [c][o]
__device__ float g_c2wT[HALF * 3 * HALF];      // [(i*3+dk)][o]
__device__ float g_c3wT[HALF * DLOI];          // [i][o]
__device__ float g_bn1s[DLOI], g_bn1t[DLOI];
__device__ float g_bn2s[HALF], g_bn2t[HALF];
__device__ float g_bn3s[HALF], g_bn3t[HALF];

// ---------------- prep: transpose weights, fold BN ----------------
__global__ void prep_kernel(const float* __restrict__ w_fc1,
                            const float* __restrict__ bn1,
                            const float* __restrict__ c1w,
                            const float* __restrict__ bn2,
                            const float* __restrict__ c2w,
                            const float* __restrict__ bn3,
                            const float* __restrict__ c3w)
{
    int t = blockIdx.x * blockDim.x + threadIdx.x;
    int stride = gridDim.x * blockDim.x;
    for (int idx = t; idx < DLOI * CIN; idx += stride) {
        int o = idx / CIN, k = idx % CIN;
        g_wfc1T[k * DLOI + o] = w_fc1[idx];
    }
    for (int idx = t; idx < HALF * DLOI; idx += stride) {
        int o = idx / DLOI, c = idx % DLOI;
        g_c1wT[c * HALF + o] = c1w[idx];
    }
    for (int idx = t; idx < HALF * HALF * 3; idx += stride) {
        int o = idx / (HALF * 3), r = idx % (HALF * 3);
        g_c2wT[r * HALF + o] = c2w[idx];
    }
    for (int idx = t; idx < DLOI * HALF; idx += stride) {
        int o = idx / HALF, i = idx % HALF;
        g_c3wT[i * DLOI + o] = c3w[idx];
    }
    for (int idx = t; idx < DLOI; idx += stride) {
        float g = bn1[idx], be = bn1[DLOI + idx], mu = bn1[2*DLOI + idx], va = bn1[3*DLOI + idx];
        float s = g * rsqrtf(va + EPSBN);
        g_bn1s[idx] = s; g_bn1t[idx] = be - mu * s;
    }
    for (int idx = t; idx < HALF; idx += stride) {
        float g = bn2[idx], be = bn2[HALF + idx], mu = bn2[2*HALF + idx], va = bn2[3*HALF + idx];
        float s = g * rsqrtf(va + EPSBN);
        g_bn2s[idx] = s; g_bn2t[idx] = be - mu * s;
        float g3 = bn3[idx], be3 = bn3[HALF + idx], mu3 = bn3[2*HALF + idx], va3 = bn3[3*HALF + idx];
        float s3 = g3 * rsqrtf(va3 + EPSBN);
        g_bn3s[idx] = s3; g_bn3t[idx] = be3 - mu3 * s3;
    }
}

// ---------------- fc1 GEMM: feature[b][c][p] x w_fc1T -> g_x NHWC ----------------
// Per batch: OUT[p][o] = sum_k feat[k][p] * wT[k][o] + b[o]
#define GM 128
#define GN 128
#define GK 16

__global__ __launch_bounds__(256) void fc1_gemm(const float* __restrict__ feat,
                                                const float* __restrict__ bfc1)
{
    int b  = blockIdx.y;
    int p0 = blockIdx.x * GM;
    const float* A = feat + (size_t)b * CIN * HW;
    float* O = g_x + (size_t)b * HW * DLOI;

    __shared__ float As[GK][GM];
    __shared__ float Bs[GK][GN];

    int t  = threadIdx.x;
    int tx = t & 15;     // output group
    int ty = t >> 4;     // pixel group

    float acc[8][8];
#pragma unroll
    for (int i = 0; i < 8; i++)
#pragma unroll
        for (int j = 0; j < 8; j++) acc[i][j] = 0.0f;

    for (int kt = 0; kt < CIN; kt += GK) {
#pragma unroll
        for (int r = 0; r < 8; r++) {
            int idx = t + r * 256;
            int kk = idx >> 7, pm = idx & 127;
            As[kk][pm] = A[(kt + kk) * HW + p0 + pm];
            Bs[kk][pm] = g_wfc1T[(kt + kk) * DLOI + pm];
        }
        __syncthreads();
#pragma unroll
        for (int kk = 0; kk < GK; kk++) {
            float a[8], bb[8];
#pragma unroll
            for (int i = 0; i < 8; i++) a[i]  = As[kk][ty * 8 + i];
#pragma unroll
            for (int j = 0; j < 8; j++) bb[j] = Bs[kk][tx * 8 + j];
#pragma unroll
            for (int i = 0; i < 8; i++)
#pragma unroll
                for (int j = 0; j < 8; j++) acc[i][j] += a[i] * bb[j];
        }
        __syncthreads();
    }

    float bias[8];
#pragma unroll
    for (int j = 0; j < 8; j++) bias[j] = bfc1[tx * 8 + j];

#pragma unroll
    for (int i = 0; i < 8; i++) {
        int p = p0 + ty * 8 + i;
        float* orow = O + (size_t)p * DLOI + tx * 8;
#pragma unroll
        for (int j = 0; j < 8; j++) orow[j] = acc[i][j] + bias[j];
    }
}

// ---------------- per-line kernel: gather + maxpool + bottleneck + fc2 + softmax ----
__global__ __launch_bounds__(128) void line_head(const float* __restrict__ lines,
                                                 const float* __restrict__ c1b,
                                                 const float* __restrict__ c2b,
                                                 const float* __restrict__ c3b,
                                                 const float* __restrict__ wfc2,
                                                 const float* __restrict__ bfc2,
                                                 float* __restrict__ out)
{
    __shared__ float sh1[DLOI * 8];
    __shared__ float sh2[HALF * 8];
    __shared__ float sh3[HALF * 8];
    __shared__ float shred[16];

    int n = blockIdx.x;
    int t = threadIdx.x;
    int b = n / LQ;

    const float* ln = lines + (size_t)n * 4;
    float ax = ln[0], ay = ln[1], bx = ln[2], by = ln[3];
    const float* X = g_x + (size_t)b * HW * DLOI;

    // gather 32 points bilinear (channel = t) + maxpool4
    float vpool[8];
#pragma unroll
    for (int p = 0; p < 8; p++) {
        float m = -INFINITY;
#pragma unroll
        for (int kk = 0; kk < 4; kk++) {
            int k = p * 4 + kk;
            float lam = (float)k * (1.0f / 31.0f);
            float px = ax * lam + bx * (1.0f - lam) - 0.5f;
            float py = ay * lam + by * (1.0f - lam) - 0.5f;
            float px0 = fminf(fmaxf(floorf(px), 0.0f), 255.0f);
            float py0 = fminf(fmaxf(floorf(py), 0.0f), 255.0f);
            float px1 = fminf(px0 + 1.0f, 255.0f);
            float py1 = fminf(py0 + 1.0f, 255.0f);
            int i0 = (int)px0, j0 = (int)py0, i1 = (int)px1, j1 = (int)py1;
            float w00 = (px1 - px) * (py1 - py);
            float w10 = (px - px0) * (py1 - py);
            float w01 = (px1 - px) * (py - py0);
            float w11 = (px - px0) * (py - py0);
            float v = X[((i0 << 8) + j0) * DLOI + t] * w00
                    + X[((i1 << 8) + j0) * DLOI + t] * w10
                    + X[((i0 << 8) + j1) * DLOI + t] * w01
                    + X[((i1 << 8) + j1) * DLOI + t] * w11;
            m = fmaxf(m, v);
        }
        vpool[p] = m;
    }

    // bn1 + relu -> sh1 (c-major, 8 contiguous)
    {
        float s1 = g_bn1s[t], t1 = g_bn1t[t];
#pragma unroll
        for (int p = 0; p < 8; p++) sh1[t * 8 + p] = fmaxf(vpool[p] * s1 + t1, 0.0f);
    }
    __syncthreads();

    int o = t & 63, half = t >> 6, pb = half * 4;

    // c1: [64,128] x [128,8] -> [64,8]; thread (o, half) does 4 p's
    float acc1[4] = {0.f, 0.f, 0.f, 0.f};
#pragma unroll 4
    for (int c = 0; c < DLOI; c++) {
        float w = g_c1wT[c * HALF + o];
        float4 h = *(const float4*)&sh1[c * 8 + pb];
        acc1[0] += w * h.x; acc1[1] += w * h.y; acc1[2] += w * h.z; acc1[3] += w * h.w;
    }
    {
        float bias = c1b[o], s2 = g_bn2s[o], t2 = g_bn2t[o];
#pragma unroll
        for (int j = 0; j < 4; j++)
            sh2[o * 8 + pb + j] = fmaxf((acc1[j] + bias) * s2 + t2, 0.0f);
    }
    __syncthreads();

    // c2: conv1d k=3 pad=1 over p, [64,64,3]
    float acc2[4] = {0.f, 0.f, 0.f, 0.f};
#pragma unroll 2
    for (int i = 0; i < HALF; i++) {
        float4 r0 = *(const float4*)&sh2[i * 8];
        float4 r1 = *(const float4*)&sh2[i * 8 + 4];
        float h[6];
        if (half == 0) { h[0] = 0.f;  h[1] = r0.x; h[2] = r0.y; h[3] = r0.z; h[4] = r0.w; h[5] = r1.x; }
        else           { h[0] = r0.w; h[1] = r1.x; h[2] = r1.y; h[3] = r1.z; h[4] = r1.w; h[5] = 0.f;  }
        float w0 = g_c2wT[(i * 3 + 0) * HALF + o];
        float w1 = g_c2wT[(i * 3 + 1) * HALF + o];
        float w2 = g_c2wT[(i * 3 + 2) * HALF + o];
#pragma unroll
        for (int j = 0; j < 4; j++)
            acc2[j] += w0 * h[j] + w1 * h[j + 1] + w2 * h[j + 2];
    }
    {
        float bias = c2b[o], s3 = g_bn3s[o], t3 = g_bn3t[o];
#pragma unroll
        for (int j = 0; j < 4; j++)
            sh3[o * 8 + pb + j] = fmaxf((acc2[j] + bias) * s3 + t3, 0.0f);
    }
    __syncthreads();

    // c3: [128,64] x [64,8] -> [128,8]; thread t = output channel, all 8 p's
    float acc3[8] = {0.f,0.f,0.f,0.f,0.f,0.f,0.f,0.f};
#pragma unroll 4
    for (int i = 0; i < HALF; i++) {
        float w = g_c3wT[i * DLOI + t];
        float4 r0 = *(const float4*)&sh3[i * 8];
        float4 r1 = *(const float4*)&sh3[i * 8 + 4];
        acc3[0] += w * r0.x; acc3[1] += w * r0.y; acc3[2] += w * r0.z; acc3[3] += w * r0.w;
        acc3[4] += w * r1.x; acc3[5] += w * r1.y; acc3[6] += w * r1.z; acc3[7] += w * r1.w;
    }
    float bias3 = c3b[t];
    float ry[8];
#pragma unroll
    for (int p = 0; p < 8; p++) ry[p] = fmaxf(vpool[p] + acc3[p] + bias3, 0.0f);

    // fc2 partials: flat index = t*8 + p
    float part[4];
#pragma unroll
    for (int q = 0; q < 4; q++) {
        const float* wq = wfc2 + q * (DLOI * 8) + t * 8;
        float4 w0 = *(const float4*)wq;
        float4 w1 = *(const float4*)(wq + 4);
        part[q] = ry[0] * w0.x + ry[1] * w0.y + ry[2] * w0.z + ry[3] * w0.w
                + ry[4] * w1.x + ry[5] * w1.y + ry[6] * w1.z + ry[7] * w1.w;
    }
#pragma unroll
    for (int q = 0; q < 4; q++) {
        float v = part[q];
#pragma unroll
        for (int off = 16; off; off >>= 1) v += __shfl_down_sync(0xffffffffu, v, off);
        part[q] = v;
    }
    int lane = t & 31, wid = t >> 5;
    if (lane == 0) {
#pragma unroll
        for (int q = 0; q < 4; q++) shred[wid * 4 + q] = part[q];
    }
    __syncthreads();
    if (t == 0) {
        float z[4];
#pragma unroll
        for (int q = 0; q < 4; q++)
            z[q] = shred[q] + shred[4 + q] + shred[8 + q] + shred[12 + q] + bfc2[q];
        float m = fmaxf(fmaxf(z[0], z[1]), fmaxf(z[2], z[3]));
        float e[4]; float sum = 0.f;
#pragma unroll
        for (int q = 0; q < 4; q++) { e[q] = expf(z[q] - m); sum += e[q]; }
        float inv = 1.0f / sum;
#pragma unroll
        for (int q = 0; q < 4; q++) out[(size_t)n * 4 + q] = e[q] * inv;
    }
}

// ---------------- launch ----------------
extern "C" void kernel_launch(void* const* d_in, const int* in_sizes, int n_in,
                              void* d_out, int out_size)
{
    const float* feature = (const float*)d_in[0];
    const float* lines   = (const float*)d_in[1];
    const float* w_fc1   = (const float*)d_in[2];
    const float* b_fc1   = (const float*)d_in[3];
    const float* bn1     = (const float*)d_in[4];
    const float* c1_w    = (const float*)d_in[5];
    const float* c1_b    = (const float*)d_in[6];
    const float* bn2     = (const float*)d_in[7];
    const float* c2_w    = (const float*)d_in[8];
    const float* c2_b    = (const float*)d_in[9];
    const float* bn3     = (const float*)d_in[10];
    const float* c3_w    = (const float*)d_in[11];
    const float* c3_b    = (const float*)d_in[12];
    const float* w_fc2   = (const float*)d_in[13];
    const float* b_fc2   = (const float*)d_in[14];
    float* out = (float*)d_out;

    prep_kernel<<<64, 256>>>(w_fc1, bn1, c1_w, bn2, c2_w, bn3, c3_w);

    dim3 grid(HW / GM, BQ);
    fc1_gemm<<<grid, 256>>>(feature, b_fc1);

    line_head<<<BQ * LQ, 128>>>(lines, c1_b, c2_b, c3_b, w_fc2, b_fc2, out);
}

// round 5
// speedup vs baseline: 1.4043x; 1.4043x over previous
#include <cuda_runtime.h>
#include <stdint.h>
#include <math.h>

#define BQ 2
#define LQ 5000
#define CIN 256
#define DLOI 128
#define NPTS0 32
#define NPTS1 8
#define HH 256
#define HALF 64
#define HW (HH*HH)
#define EPSBN 1e-5f

// ---------------- scratch (device globals; no allocation allowed) ----------------
__device__ float g_x[BQ * HW * DLOI];          // fc1 output, NHWC  (64 MB)
__device__ float g_wfc1T[CIN * DLOI];          // [k][o]
__device__ float g_c1wT[DLOI * HALF];          // [c][o]
__device__ float g_c2wT[HALF * 3 * HALF];      // [(i*3+dk)][o]
__device__ float g_c3wT[HALF * DLOI];          // [i][o]
__device__ float g_bn1s[DLOI], g_bn1t[DLOI];
__device__ float g_bn2s[HALF], g_bn2t[HALF];
__device__ float g_bn3s[HALF], g_bn3t[HALF];

// ---------------- prep: transpose weights, fold BN ----------------
__global__ void prep_kernel(const float* __restrict__ w_fc1,
                            const float* __restrict__ bn1,
                            const float* __restrict__ c1w,
                            const float* __restrict__ bn2,
                            const float* __restrict__ c2w,
                            const float* __restrict__ bn3,
                            const float* __restrict__ c3w)
{
    int t = blockIdx.x * blockDim.x + threadIdx.x;
    int stride = gridDim.x * blockDim.x;
    for (int idx = t; idx < DLOI * CIN; idx += stride) {
        int o = idx / CIN, k = idx % CIN;
        g_wfc1T[k * DLOI + o] = w_fc1[idx];
    }
    for (int idx = t; idx < HALF * DLOI; idx += stride) {
        int o = idx / DLOI, c = idx % DLOI;
        g_c1wT[c * HALF + o] = c1w[idx];
    }
    for (int idx = t; idx < HALF * HALF * 3; idx += stride) {
        int o = idx / (HALF * 3), r = idx % (HALF * 3);
        g_c2wT[r * HALF + o] = c2w[idx];
    }
    for (int idx = t; idx < DLOI * HALF; idx += stride) {
        int o = idx / HALF, i = idx % HALF;
        g_c3wT[i * DLOI + o] = c3w[idx];
    }
    for (int idx = t; idx < DLOI; idx += stride) {
        float g = bn1[idx], be = bn1[DLOI + idx], mu = bn1[2*DLOI + idx], va = bn1[3*DLOI + idx];
        float s = g * rsqrtf(va + EPSBN);
        g_bn1s[idx] = s; g_bn1t[idx] = be - mu * s;
    }
    for (int idx = t; idx < HALF; idx += stride) {
        float g = bn2[idx], be = bn2[HALF + idx], mu = bn2[2*HALF + idx], va = bn2[3*HALF + idx];
        float s = g * rsqrtf(va + EPSBN);
        g_bn2s[idx] = s; g_bn2t[idx] = be - mu * s;
        float g3 = bn3[idx], be3 = bn3[HALF + idx], mu3 = bn3[2*HALF + idx], va3 = bn3[3*HALF + idx];
        float s3 = g3 * rsqrtf(va3 + EPSBN);
        g_bn3s[idx] = s3; g_bn3t[idx] = be3 - mu3 * s3;
    }
}

// ---------------- fc1 GEMM via tf32 mma.sync: O[p][o] = sum_k feat[k][p]*wT[k][o] + b ----
#define KT 32                   // k per smem stage
#define AS_STRIDE 132           // 128 + 4 pad (words)
#define OS_STRIDE 130           // epilogue staging stride

__device__ __forceinline__ float to_tf32(float x) {
    uint32_t r;
    asm("cvt.rna.tf32.f32 %0, %1;" : "=r"(r) : "f"(x));
    return __uint_as_float(r);
}

__device__ __forceinline__ void mma_tf32(float4& d, const float* a, const float* b) {
    asm volatile(
        "mma.sync.aligned.m16n8k8.row.col.f32.tf32.tf32.f32 "
        "{%0,%1,%2,%3}, {%4,%5,%6,%7}, {%8,%9}, {%0,%1,%2,%3};\n"
        : "+f"(d.x), "+f"(d.y), "+f"(d.z), "+f"(d.w)
        : "r"(__float_as_uint(a[0])), "r"(__float_as_uint(a[1])),
          "r"(__float_as_uint(a[2])), "r"(__float_as_uint(a[3])),
          "r"(__float_as_uint(b[0])), "r"(__float_as_uint(b[1])));
}

__global__ __launch_bounds__(256, 2) void fc1_gemm_tf32(const float* __restrict__ feat,
                                                        const float* __restrict__ bfc1)
{
    __shared__ float sm[2 * KT * AS_STRIDE];       // 33792 B; reused as Osm[64][130]
    float* As = sm;                                 // [KT][128] stride AS_STRIDE
    float* Bs = sm + KT * AS_STRIDE;

    int b  = blockIdx.y;
    int p0 = blockIdx.x * 128;
    const float* A = feat + (size_t)b * CIN * HW;
    float* O = g_x + (size_t)b * HW * DLOI;

    int t    = threadIdx.x;
    int w    = t >> 5;
    int lane = t & 31;
    int g    = lane >> 2;        // 0..7
    int tg   = lane & 3;         // 0..3
    int warp_m = w & 3;          // 0..3  -> rows m_base..m_base+31
    int warp_n = w >> 2;         // 0..1  -> cols n_base..n_base+63
    int m_base = warp_m * 32;
    int n_base = warp_n * 64;

    float4 acc[2][8];
#pragma unroll
    for (int mi = 0; mi < 2; mi++)
#pragma unroll
        for (int ni = 0; ni < 8; ni++) acc[mi][ni] = make_float4(0.f, 0.f, 0.f, 0.f);

    for (int k0 = 0; k0 < CIN; k0 += KT) {
        // stage A and B tiles (tf32-rounded), fully coalesced float4
#pragma unroll
        for (int i = 0; i < 4; i++) {
            int f  = t + 256 * i;          // 0..1023 float4 index
            int kk = f >> 5;
            int pm = (f & 31) * 4;
            float4 va = *(const float4*)&A[(size_t)(k0 + kk) * HW + p0 + pm];
            va.x = to_tf32(va.x); va.y = to_tf32(va.y); va.z = to_tf32(va.z); va.w = to_tf32(va.w);
            *(float4*)&As[kk * AS_STRIDE + pm] = va;
            float4 vb = *(const float4*)&g_wfc1T[(k0 + kk) * DLOI + pm];
            vb.x = to_tf32(vb.x); vb.y = to_tf32(vb.y); vb.z = to_tf32(vb.z); vb.w = to_tf32(vb.w);
            *(float4*)&Bs[kk * AS_STRIDE + pm] = vb;
        }
        __syncthreads();

#pragma unroll
        for (int ks = 0; ks < KT / 8; ks++) {
            int kb = ks * 8;
            float afr[2][4];
#pragma unroll
            for (int mi = 0; mi < 2; mi++) {
                int r = m_base + mi * 16 + g;
                afr[mi][0] = As[(kb + tg) * AS_STRIDE + r];
                afr[mi][1] = As[(kb + tg) * AS_STRIDE + r + 8];
                afr[mi][2] = As[(kb + tg + 4) * AS_STRIDE + r];
                afr[mi][3] = As[(kb + tg + 4) * AS_STRIDE + r + 8];
            }
            float bfr[8][2];
#pragma unroll
            for (int ni = 0; ni < 8; ni++) {
                int c = n_base + ni * 8 + g;
                bfr[ni][0] = Bs[(kb + tg) * AS_STRIDE + c];
                bfr[ni][1] = Bs[(kb + tg + 4) * AS_STRIDE + c];
            }
#pragma unroll
            for (int mi = 0; mi < 2; mi++)
#pragma unroll
                for (int ni = 0; ni < 8; ni++)
                    mma_tf32(acc[mi][ni], afr[mi], bfr[ni]);
        }
        __syncthreads();
    }

    // epilogue: stage 64 rows at a time through smem for coalesced NHWC stores
    float* Osm = sm;   // [64][OS_STRIDE]
#pragma unroll
    for (int chunk = 0; chunk < 2; chunk++) {
        if ((warp_m >> 1) == chunk) {
            int rl = (warp_m & 1) * 32;
#pragma unroll
            for (int mi = 0; mi < 2; mi++) {
#pragma unroll
                for (int ni = 0; ni < 8; ni++) {
                    int row = rl + mi * 16 + g;
                    int col = n_base + ni * 8 + 2 * tg;
                    float4 d = acc[mi][ni];
                    *(float2*)&Osm[row * OS_STRIDE + col]       = make_float2(d.x, d.y);
                    *(float2*)&Osm[(row + 8) * OS_STRIDE + col] = make_float2(d.z, d.w);
                }
            }
        }
        __syncthreads();
#pragma unroll
        for (int i = 0; i < 8; i++) {
            int f   = t + 256 * i;          // 0..2047 float4 index (64*32)
            int row = f >> 5;
            int o4  = (f & 31) * 4;
            float4 v;
            v.x = Osm[row * OS_STRIDE + o4]     + bfc1[o4];
            v.y = Osm[row * OS_STRIDE + o4 + 1] + bfc1[o4 + 1];
            v.z = Osm[row * OS_STRIDE + o4 + 2] + bfc1[o4 + 2];
            v.w = Osm[row * OS_STRIDE + o4 + 3] + bfc1[o4 + 3];
            *(float4*)&O[(size_t)(p0 + chunk * 64 + row) * DLOI + o4] = v;
        }
        __syncthreads();
    }
}

// ---------------- per-line kernel: gather + maxpool + bottleneck + fc2 + softmax ----
__global__ __launch_bounds__(128) void line_head(const float* __restrict__ lines,
                                                 const float* __restrict__ c1b,
                                                 const float* __restrict__ c2b,
                                                 const float* __restrict__ c3b,
                                                 const float* __restrict__ wfc2,
                                                 const float* __restrict__ bfc2,
                                                 float* __restrict__ out)
{
    __shared__ float sh1[DLOI * 8];
    __shared__ float sh2[HALF * 8];
    __shared__ float sh3[HALF * 8];
    __shared__ float shred[16];

    int n = blockIdx.x;
    int t = threadIdx.x;
    int b = n / LQ;

    const float* ln = lines + (size_t)n * 4;
    float ax = ln[0], ay = ln[1], bx = ln[2], by = ln[3];
    const float* X = g_x + (size_t)b * HW * DLOI;

    // gather 32 points bilinear (channel = t) + maxpool4
    float vpool[8];
#pragma unroll
    for (int p = 0; p < 8; p++) {
        float m = -INFINITY;
#pragma unroll
        for (int kk = 0; kk < 4; kk++) {
            int k = p * 4 + kk;
            float lam = (float)k * (1.0f / 31.0f);
            float px = ax * lam + bx * (1.0f - lam) - 0.5f;
            float py = ay * lam + by * (1.0f - lam) - 0.5f;
            float px0 = fminf(fmaxf(floorf(px), 0.0f), 255.0f);
            float py0 = fminf(fmaxf(floorf(py), 0.0f), 255.0f);
            float px1 = fminf(px0 + 1.0f, 255.0f);
            float py1 = fminf(py0 + 1.0f, 255.0f);
            int i0 = (int)px0, j0 = (int)py0, i1 = (int)px1, j1 = (int)py1;
            float w00 = (px1 - px) * (py1 - py);
            float w10 = (px - px0) * (py1 - py);
            float w01 = (px1 - px) * (py - py0);
            float w11 = (px - px0) * (py - py0);
            float v = X[((i0 << 8) + j0) * DLOI + t] * w00
                    + X[((i1 << 8) + j0) * DLOI + t] * w10
                    + X[((i0 << 8) + j1) * DLOI + t] * w01
                    + X[((i1 << 8) + j1) * DLOI + t] * w11;
            m = fmaxf(m, v);
        }
        vpool[p] = m;
    }

    // bn1 + relu -> sh1 (c-major, 8 contiguous)
    {
        float s1 = g_bn1s[t], t1 = g_bn1t[t];
#pragma unroll
        for (int p = 0; p < 8; p++) sh1[t * 8 + p] = fmaxf(vpool[p] * s1 + t1, 0.0f);
    }
    __syncthreads();

    int o = t & 63, half = t >> 6, pb = half * 4;

    // c1: [64,128] x [128,8] -> [64,8]; thread (o, half) does 4 p's
    float acc1[4] = {0.f, 0.f, 0.f, 0.f};
#pragma unroll 4
    for (int c = 0; c < DLOI; c++) {
        float w = g_c1wT[c * HALF + o];
        float4 h = *(const float4*)&sh1[c * 8 + pb];
        acc1[0] += w * h.x; acc1[1] += w * h.y; acc1[2] += w * h.z; acc1[3] += w * h.w;
    }
    {
        float bias = c1b[o], s2 = g_bn2s[o], t2 = g_bn2t[o];
#pragma unroll
        for (int j = 0; j < 4; j++)
            sh2[o * 8 + pb + j] = fmaxf((acc1[j] + bias) * s2 + t2, 0.0f);
    }
    __syncthreads();

    // c2: conv1d k=3 pad=1 over p, [64,64,3]
    float acc2[4] = {0.f, 0.f, 0.f, 0.f};
#pragma unroll 2
    for (int i = 0; i < HALF; i++) {
        float4 r0 = *(const float4*)&sh2[i * 8];
        float4 r1 = *(const float4*)&sh2[i * 8 + 4];
        float h[6];
        if (half == 0) { h[0] = 0.f;  h[1] = r0.x; h[2] = r0.y; h[3] = r0.z; h[4] = r0.w; h[5] = r1.x; }
        else           { h[0] = r0.w; h[1] = r1.x; h[2] = r1.y; h[3] = r1.z; h[4] = r1.w; h[5] = 0.f;  }
        float w0 = g_c2wT[(i * 3 + 0) * HALF + o];
        float w1 = g_c2wT[(i * 3 + 1) * HALF + o];
        float w2 = g_c2wT[(i * 3 + 2) * HALF + o];
#pragma unroll
        for (int j = 0; j < 4; j++)
            acc2[j] += w0 * h[j] + w1 * h[j + 1] + w2 * h[j + 2];
    }
    {
        float bias = c2b[o], s3 = g_bn3s[o], t3 = g_bn3t[o];
#pragma unroll
        for (int j = 0; j < 4; j++)
            sh3[o * 8 + pb + j] = fmaxf((acc2[j] + bias) * s3 + t3, 0.0f);
    }
    __syncthreads();

    // c3: [128,64] x [64,8] -> [128,8]; thread t = output channel, all 8 p's
    float acc3[8] = {0.f,0.f,0.f,0.f,0.f,0.f,0.f,0.f};
#pragma unroll 4
    for (int i = 0; i < HALF; i++) {
        float w = g_c3wT[i * DLOI + t];
        float4 r0 = *(const float4*)&sh3[i * 8];
        float4 r1 = *(const float4*)&sh3[i * 8 + 4];
        acc3[0] += w * r0.x; acc3[1] += w * r0.y; acc3[2] += w * r0.z; acc3[3] += w * r0.w;
        acc3[4] += w * r1.x; acc3[5] += w * r1.y; acc3[6] += w * r1.z; acc3[7] += w * r1.w;
    }
    float bias3 = c3b[t];
    float ry[8];
#pragma unroll
    for (int p = 0; p < 8; p++) ry[p] = fmaxf(vpool[p] + acc3[p] + bias3, 0.0f);

    // fc2 partials: flat index = t*8 + p
    float part[4];
#pragma unroll
    for (int q = 0; q < 4; q++) {
        const float* wq = wfc2 + q * (DLOI * 8) + t * 8;
        float4 w0 = *(const float4*)wq;
        float4 w1 = *(const float4*)(wq + 4);
        part[q] = ry[0] * w0.x + ry[1] * w0.y + ry[2] * w0.z + ry[3] * w0.w
                + ry[4] * w1.x + ry[5] * w1.y + ry[6] * w1.z + ry[7] * w1.w;
    }
#pragma unroll
    for (int q = 0; q < 4; q++) {
        float v = part[q];
#pragma unroll
        for (int off = 16; off; off >>= 1) v += __shfl_down_sync(0xffffffffu, v, off);
        part[q] = v;
    }
    int lane = t & 31, wid = t >> 5;
    if (lane == 0) {
#pragma unroll
        for (int q = 0; q < 4; q++) shred[wid * 4 + q] = part[q];
    }
    __syncthreads();
    if (t == 0) {
        float z[4];
#pragma unroll
        for (int q = 0; q < 4; q++)
            z[q] = shred[q] + shred[4 + q] + shred[8 + q] + shred[12 + q] + bfc2[q];
        float m = fmaxf(fmaxf(z[0], z[1]), fmaxf(z[2], z[3]));
        float e[4]; float sum = 0.f;
#pragma unroll
        for (int q = 0; q < 4; q++) { e[q] = expf(z[q] - m); sum += e[q]; }
        float inv = 1.0f / sum;
#pragma unroll
        for (int q = 0; q < 4; q++) out[(size_t)n * 4 + q] = e[q] * inv;
    }
}

// ---------------- launch ----------------
extern "C" void kernel_launch(void* const* d_in, const int* in_sizes, int n_in,
                              void* d_out, int out_size)
{
    const float* feature = (const float*)d_in[0];
    const float* lines   = (const float*)d_in[1];
    const float* w_fc1   = (const float*)d_in[2];
    const float* b_fc1   = (const float*)d_in[3];
    const float* bn1     = (const float*)d_in[4];
    const float* c1_w    = (const float*)d_in[5];
    const float* c1_b    = (const float*)d_in[6];
    const float* bn2     = (const float*)d_in[7];
    const float* c2_w    = (const float*)d_in[8];
    const float* c2_b    = (const float*)d_in[9];
    const float* bn3     = (const float*)d_in[10];
    const float* c3_w    = (const float*)d_in[11];
    const float* c3_b    = (const float*)d_in[12];
    const float* w_fc2   = (const float*)d_in[13];
    const float* b_fc2   = (const float*)d_in[14];
    float* out = (float*)d_out;

    prep_kernel<<<64, 256>>>(w_fc1, bn1, c1_w, bn2, c2_w, bn3, c3_w);

    dim3 grid(HW / 128, BQ);
    fc1_gemm_tf32<<<grid, 256>>>(feature, b_fc1);

    line_head<<<BQ * LQ, 128>>>(lines, c1_b, c2_b, c3_b, w_fc2, b_fc2, out);
}

// round 6
// speedup vs baseline: 1.6049x; 1.1428x over previous
#include <cuda_runtime.h>
#include <cuda_fp16.h>
#include <stdint.h>
#include <math.h>

#define BQ 2
#define LQ 5000
#define CIN 256
#define DLOI 128
#define NPTS0 32
#define NPTS1 8
#define HH 256
#define HALF 64
#define HW (HH*HH)
#define EPSBN 1e-5f

// ---------------- scratch (device globals; no allocation allowed) ----------------
__device__ __half g_xh[BQ * HW * DLOI];        // fc1 output, NHWC, fp16 (33.5 MB)
__device__ float g_wfc1T[CIN * DLOI];          // [k][o], tf32-rounded
__device__ float g_c1wT[DLOI * HALF];          // [c][o]
__device__ float g_c2wT[HALF * 3 * HALF];      // [(i*3+dk)][o]
__device__ float g_c3wT[HALF * DLOI];          // [i][o]
__device__ float g_bn1s[DLOI], g_bn1t[DLOI];
__device__ float g_bn2s[HALF], g_bn2t[HALF];
__device__ float g_bn3s[HALF], g_bn3t[HALF];

__device__ __forceinline__ float to_tf32(float x) {
    uint32_t r;
    asm("cvt.rna.tf32.f32 %0, %1;" : "=r"(r) : "f"(x));
    return __uint_as_float(r);
}

// ---------------- prep: transpose weights, fold BN ----------------
__global__ void prep_kernel(const float* __restrict__ w_fc1,
                            const float* __restrict__ bn1,
                            const float* __restrict__ c1w,
                            const float* __restrict__ bn2,
                            const float* __restrict__ c2w,
                            const float* __restrict__ bn3,
                            const float* __restrict__ c3w)
{
    int t = blockIdx.x * blockDim.x + threadIdx.x;
    int stride = gridDim.x * blockDim.x;
    for (int idx = t; idx < DLOI * CIN; idx += stride) {
        int o = idx / CIN, k = idx % CIN;
        g_wfc1T[k * DLOI + o] = to_tf32(w_fc1[idx]);
    }
    for (int idx = t; idx < HALF * DLOI; idx += stride) {
        int o = idx / DLOI, c = idx % DLOI;
        g_c1wT[c * HALF + o] = c1w[idx];
    }
    for (int idx = t; idx < HALF * HALF * 3; idx += stride) {
        int o = idx / (HALF * 3), r = idx % (HALF * 3);
        g_c2wT[r * HALF + o] = c2w[idx];
    }
    for (int idx = t; idx < DLOI * HALF; idx += stride) {
        int o = idx / HALF, i = idx % HALF;
        g_c3wT[i * DLOI + o] = c3w[idx];
    }
    for (int idx = t; idx < DLOI; idx += stride) {
        float g = bn1[idx], be = bn1[DLOI + idx], mu = bn1[2*DLOI + idx], va = bn1[3*DLOI + idx];
        float s = g * rsqrtf(va + EPSBN);
        g_bn1s[idx] = s; g_bn1t[idx] = be - mu * s;
    }
    for (int idx = t; idx < HALF; idx += stride) {
        float g = bn2[idx], be = bn2[HALF + idx], mu = bn2[2*HALF + idx], va = bn2[3*HALF + idx];
        float s = g * rsqrtf(va + EPSBN);
        g_bn2s[idx] = s; g_bn2t[idx] = be - mu * s;
        float g3 = bn3[idx], be3 = bn3[HALF + idx], mu3 = bn3[2*HALF + idx], va3 = bn3[3*HALF + idx];
        float s3 = g3 * rsqrtf(va3 + EPSBN);
        g_bn3s[idx] = s3; g_bn3t[idx] = be3 - mu3 * s3;
    }
}

// ---------------- fc1 GEMM via tf32 mma.sync + cp.async double buffering ----------
#define KT 32                   // k per smem stage
#define AS_STRIDE 132           // 128 + 4 pad (words)
#define OSH 136                 // epilogue half staging stride (halves)
#define STAGE_FLOATS (2 * KT * AS_STRIDE)
#define FC1_SMEM (2 * STAGE_FLOATS * 4)

__device__ __forceinline__ void cp_async16(void* smem_ptr, const void* gmem_ptr) {
    uint32_t s = (uint32_t)__cvta_generic_to_shared(smem_ptr);
    asm volatile("cp.async.cg.shared.global [%0], [%1], 16;\n" :: "r"(s), "l"(gmem_ptr));
}

__device__ __forceinline__ void mma_tf32(float4& d, const float* a, const float* b) {
    asm volatile(
        "mma.sync.aligned.m16n8k8.row.col.f32.tf32.tf32.f32 "
        "{%0,%1,%2,%3}, {%4,%5,%6,%7}, {%8,%9}, {%0,%1,%2,%3};\n"
        : "+f"(d.x), "+f"(d.y), "+f"(d.z), "+f"(d.w)
        : "r"(__float_as_uint(a[0])), "r"(__float_as_uint(a[1])),
          "r"(__float_as_uint(a[2])), "r"(__float_as_uint(a[3])),
          "r"(__float_as_uint(b[0])), "r"(__float_as_uint(b[1])));
}

__global__ __launch_bounds__(256) void fc1_gemm_tf32(const float* __restrict__ feat,
                                                     const float* __restrict__ bfc1)
{
    extern __shared__ float sm[];

    int b  = blockIdx.y;
    int p0 = blockIdx.x * 128;
    const float* A = feat + (size_t)b * CIN * HW;
    __half* O = g_xh + (size_t)b * HW * DLOI;

    int t    = threadIdx.x;
    int w    = t >> 5;
    int lane = t & 31;
    int g    = lane >> 2;        // 0..7
    int tg   = lane & 3;         // 0..3
    int warp_m = w & 3;          // 0..3
    int warp_n = w >> 2;         // 0..1
    int m_base = warp_m * 32;
    int n_base = warp_n * 64;

    float4 acc[2][8];
#pragma unroll
    for (int mi = 0; mi < 2; mi++)
#pragma unroll
        for (int ni = 0; ni < 8; ni++) acc[mi][ni] = make_float4(0.f, 0.f, 0.f, 0.f);

    auto issue_stage = [&](int s) {
        float* As = sm + (s & 1) * STAGE_FLOATS;
        float* Bs = As + KT * AS_STRIDE;
        int k0 = s * KT;
#pragma unroll
        for (int i = 0; i < 4; i++) {
            int f  = t + 256 * i;          // 0..1023 float4 index
            int kk = f >> 5;
            int pm = (f & 31) * 4;
            cp_async16(&As[kk * AS_STRIDE + pm], &A[(size_t)(k0 + kk) * HW + p0 + pm]);
            cp_async16(&Bs[kk * AS_STRIDE + pm], &g_wfc1T[(k0 + kk) * DLOI + pm]);
        }
        asm volatile("cp.async.commit_group;\n");
    };

    issue_stage(0);

    const int NS = CIN / KT;     // 8
    for (int s = 0; s < NS; s++) {
        if (s + 1 < NS) {
            issue_stage(s + 1);
            asm volatile("cp.async.wait_group 1;\n");
        } else {
            asm volatile("cp.async.wait_group 0;\n");
        }
        __syncthreads();

        float* As = sm + (s & 1) * STAGE_FLOATS;
        float* Bs = As + KT * AS_STRIDE;

#pragma unroll
        for (int ks = 0; ks < KT / 8; ks++) {
            int kb = ks * 8;
            float afr[2][4];
#pragma unroll
            for (int mi = 0; mi < 2; mi++) {
                int r = m_base + mi * 16 + g;
                afr[mi][0] = As[(kb + tg) * AS_STRIDE + r];
                afr[mi][1] = As[(kb + tg) * AS_STRIDE + r + 8];
                afr[mi][2] = As[(kb + tg + 4) * AS_STRIDE + r];
                afr[mi][3] = As[(kb + tg + 4) * AS_STRIDE + r + 8];
            }
            float bfr[8][2];
#pragma unroll
            for (int ni = 0; ni < 8; ni++) {
                int c = n_base + ni * 8 + g;
                bfr[ni][0] = Bs[(kb + tg) * AS_STRIDE + c];
                bfr[ni][1] = Bs[(kb + tg + 4) * AS_STRIDE + c];
            }
#pragma unroll
            for (int mi = 0; mi < 2; mi++)
#pragma unroll
                for (int ni = 0; ni < 8; ni++)
                    mma_tf32(acc[mi][ni], afr[mi], bfr[ni]);
        }
        __syncthreads();
    }

    // bias per fragment column pair
    float bx[8], by[8];
#pragma unroll
    for (int ni = 0; ni < 8; ni++) {
        int c = n_base + ni * 8 + 2 * tg;
        bx[ni] = bfc1[c];
        by[ni] = bfc1[c + 1];
    }

    // epilogue: stage 64 rows at a time through smem (fp16) for coalesced NHWC stores
    __half* Osm = (__half*)sm;   // [64][OSH]
#pragma unroll
    for (int chunk = 0; chunk < 2; chunk++) {
        if ((warp_m >> 1) == chunk) {
            int rl = (warp_m & 1) * 32;
#pragma unroll
            for (int mi = 0; mi < 2; mi++) {
#pragma unroll
                for (int ni = 0; ni < 8; ni++) {
                    int row = rl + mi * 16 + g;
                    int col = n_base + ni * 8 + 2 * tg;
                    float4 d = acc[mi][ni];
                    *(__half2*)&Osm[row * OSH + col] =
                        __floats2half2_rn(d.x + bx[ni], d.y + by[ni]);
                    *(__half2*)&Osm[(row + 8) * OSH + col] =
                        __floats2half2_rn(d.z + bx[ni], d.w + by[ni]);
                }
            }
        }
        __syncthreads();
#pragma unroll
        for (int i = 0; i < 4; i++) {
            int f   = t + 256 * i;          // 0..1023; 16 x uint4 (8 halves) per row
            int row = f >> 4;
            int h0  = (f & 15) * 8;
            uint4 v = *(const uint4*)&Osm[row * OSH + h0];
            *(uint4*)&O[(size_t)(p0 + chunk * 64 + row) * DLOI + h0] = v;
        }
        __syncthreads();
    }
}

// ---------------- per-line kernel: gather + maxpool + bottleneck + fc2 + softmax ----
__global__ __launch_bounds__(128) void line_head(const float* __restrict__ lines,
                                                 const float* __restrict__ c1b,
                                                 const float* __restrict__ c2b,
                                                 const float* __restrict__ c3b,
                                                 const float* __restrict__ wfc2,
                                                 const float* __restrict__ bfc2,
                                                 float* __restrict__ out)
{
    __shared__ float sh1[DLOI * 8];
    __shared__ float sh2[HALF * 8];
    __shared__ float sh3[HALF * 8];
    __shared__ float shred[16];

    int n = blockIdx.x;
    int t = threadIdx.x;
    int b = n / LQ;

    const float* ln = lines + (size_t)n * 4;
    float ax = ln[0], ay = ln[1], bx = ln[2], by = ln[3];
    const __half* X = g_xh + (size_t)b * HW * DLOI + t;

    // gather 32 points bilinear (channel = t) + maxpool4
    float vpool[8];
#pragma unroll
    for (int p = 0; p < 8; p++) {
        float m = -INFINITY;
#pragma unroll
        for (int kk = 0; kk < 4; kk++) {
            int k = p * 4 + kk;
            float lam = (float)k * (1.0f / 31.0f);
            float px = ax * lam + bx * (1.0f - lam) - 0.5f;
            float py = ay * lam + by * (1.0f - lam) - 0.5f;
            float px0 = fminf(fmaxf(floorf(px), 0.0f), 255.0f);
            float py0 = fminf(fmaxf(floorf(py), 0.0f), 255.0f);
            float px1 = fminf(px0 + 1.0f, 255.0f);
            float py1 = fminf(py0 + 1.0f, 255.0f);
            int i0 = (int)px0, j0 = (int)py0, i1 = (int)px1, j1 = (int)py1;
            float w00 = (px1 - px) * (py1 - py);
            float w10 = (px - px0) * (py1 - py);
            float w01 = (px1 - px) * (py - py0);
            float w11 = (px - px0) * (py - py0);
            float v = __half2float(__ldg(X + ((i0 << 8) + j0) * DLOI)) * w00
                    + __half2float(__ldg(X + ((i1 << 8) + j0) * DLOI)) * w10
                    + __half2float(__ldg(X + ((i0 << 8) + j1) * DLOI)) * w01
                    + __half2float(__ldg(X + ((i1 << 8) + j1) * DLOI)) * w11;
            m = fmaxf(m, v);
        }
        vpool[p] = m;
    }

    // bn1 + relu -> sh1 (c-major, 8 contiguous)
    {
        float s1 = g_bn1s[t], t1 = g_bn1t[t];
#pragma unroll
        for (int p = 0; p < 8; p++) sh1[t * 8 + p] = fmaxf(vpool[p] * s1 + t1, 0.0f);
    }
    __syncthreads();

    int o = t & 63, half = t >> 6, pb = half * 4;

    // c1: [64,128] x [128,8] -> [64,8]; thread (o, half) does 4 p's
    float acc1[4] = {0.f, 0.f, 0.f, 0.f};
#pragma unroll 4
    for (int c = 0; c < DLOI; c++) {
        float w = g_c1wT[c * HALF + o];
        float4 h = *(const float4*)&sh1[c * 8 + pb];
        acc1[0] += w * h.x; acc1[1] += w * h.y; acc1[2] += w * h.z; acc1[3] += w * h.w;
    }
    {
        float bias = c1b[o], s2 = g_bn2s[o], t2 = g_bn2t[o];
#pragma unroll
        for (int j = 0; j < 4; j++)
            sh2[o * 8 + pb + j] = fmaxf((acc1[j] + bias) * s2 + t2, 0.0f);
    }
    __syncthreads();

    // c2: conv1d k=3 pad=1 over p, [64,64,3]
    float acc2[4] = {0.f, 0.f, 0.f, 0.f};
#pragma unroll 2
    for (int i = 0; i < HALF; i++) {
        float4 r0 = *(const float4*)&sh2[i * 8];
        float4 r1 = *(const float4*)&sh2[i * 8 + 4];
        float h[6];
        if (half == 0) { h[0] = 0.f;  h[1] = r0.x; h[2] = r0.y; h[3] = r0.z; h[4] = r0.w; h[5] = r1.x; }
        else           { h[0] = r0.w; h[1] = r1.x; h[2] = r1.y; h[3] = r1.z; h[4] = r1.w; h[5] = 0.f;  }
        float w0 = g_c2wT[(i * 3 + 0) * HALF + o];
        float w1 = g_c2wT[(i * 3 + 1) * HALF + o];
        float w2 = g_c2wT[(i * 3 + 2) * HALF + o];
#pragma unroll
        for (int j = 0; j < 4; j++)
            acc2[j] += w0 * h[j] + w1 * h[j + 1] + w2 * h[j + 2];
    }
    {
        float bias = c2b[o], s3 = g_bn3s[o], t3 = g_bn3t[o];
#pragma unroll
        for (int j = 0; j < 4; j++)
            sh3[o * 8 + pb + j] = fmaxf((acc2[j] + bias) * s3 + t3, 0.0f);
    }
    __syncthreads();

    // c3: [128,64] x [64,8] -> [128,8]; thread t = output channel, all 8 p's
    float acc3[8] = {0.f,0.f,0.f,0.f,0.f,0.f,0.f,0.f};
#pragma unroll 4
    for (int i = 0; i < HALF; i++) {
        float w = g_c3wT[i * DLOI + t];
        float4 r0 = *(const float4*)&sh3[i * 8];
        float4 r1 = *(const float4*)&sh3[i * 8 + 4];
        acc3[0] += w * r0.x; acc3[1] += w * r0.y; acc3[2] += w * r0.z; acc3[3] += w * r0.w;
        acc3[4] += w * r1.x; acc3[5] += w * r1.y; acc3[6] += w * r1.z; acc3[7] += w * r1.w;
    }
    float bias3 = c3b[t];
    float ry[8];
#pragma unroll
    for (int p = 0; p < 8; p++) ry[p] = fmaxf(vpool[p] + acc3[p] + bias3, 0.0f);

    // fc2 partials: flat index = t*8 + p
    float part[4];
#pragma unroll
    for (int q = 0; q < 4; q++) {
        const float* wq = wfc2 + q * (DLOI * 8) + t * 8;
        float4 w0 = *(const float4*)wq;
        float4 w1 = *(const float4*)(wq + 4);
        part[q] = ry[0] * w0.x + ry[1] * w0.y + ry[2] * w0.z + ry[3] * w0.w
                + ry[4] * w1.x + ry[5] * w1.y + ry[6] * w1.z + ry[7] * w1.w;
    }
#pragma unroll
    for (int q = 0; q < 4; q++) {
        float v = part[q];
#pragma unroll
        for (int off = 16; off; off >>= 1) v += __shfl_down_sync(0xffffffffu, v, off);
        part[q] = v;
    }
    int lane = t & 31, wid = t >> 5;
    if (lane == 0) {
#pragma unroll
        for (int q = 0; q < 4; q++) shred[wid * 4 + q] = part[q];
    }
    __syncthreads();
    if (t == 0) {
        float z[4];
#pragma unroll
        for (int q = 0; q < 4; q++)
            z[q] = shred[q] + shred[4 + q] + shred[8 + q] + shred[12 + q] + bfc2[q];
        float m = fmaxf(fmaxf(z[0], z[1]), fmaxf(z[2], z[3]));
        float e[4]; float sum = 0.f;
#pragma unroll
        for (int q = 0; q < 4; q++) { e[q] = expf(z[q] - m); sum += e[q]; }
        float inv = 1.0f / sum;
#pragma unroll
        for (int q = 0; q < 4; q++) out[(size_t)n * 4 + q] = e[q] * inv;
    }
}

// ---------------- launch ----------------
extern "C" void kernel_launch(void* const* d_in, const int* in_sizes, int n_in,
                              void* d_out, int out_size)
{
    const float* feature = (const float*)d_in[0];
    const float* lines   = (const float*)d_in[1];
    const float* w_fc1   = (const float*)d_in[2];
    const float* b_fc1   = (const float*)d_in[3];
    const float* bn1     = (const float*)d_in[4];
    const float* c1_w    = (const float*)d_in[5];
    const float* c1_b    = (const float*)d_in[6];
    const float* bn2     = (const float*)d_in[7];
    const float* c2_w    = (const float*)d_in[8];
    const float* c2_b    = (const float*)d_in[9];
    const float* bn3     = (const float*)d_in[10];
    const float* c3_w    = (const float*)d_in[11];
    const float* c3_b    = (const float*)d_in[12];
    const float* w_fc2   = (const float*)d_in[13];
    const float* b_fc2   = (const float*)d_in[14];
    float* out = (float*)d_out;

    static int smem_set = 0;
    if (!smem_set) {
        cudaFuncSetAttribute(fc1_gemm_tf32,
                             cudaFuncAttributeMaxDynamicSharedMemorySize, FC1_SMEM);
        smem_set = 1;
    }

    prep_kernel<<<64, 256>>>(w_fc1, bn1, c1_w, bn2, c2_w, bn3, c3_w);

    dim3 grid(HW / 128, BQ);
    fc1_gemm_tf32<<<grid, 256, FC1_SMEM>>>(feature, b_fc1);

    line_head<<<BQ * LQ, 128>>>(lines, c1_b, c2_b, c3_b, w_fc2, b_fc2, out);
}

// round 7
// speedup vs baseline: 1.7223x; 1.0732x over previous
#include <cuda_runtime.h>
#include <cuda_fp16.h>
#include <stdint.h>
#include <math.h>

#define BQ 2
#define LQ 5000
#define CIN 256
#define DLOI 128
#define NPTS0 32
#define NPTS1 8
#define HH 256
#define HALF 64
#define HW (HH*HH)
#define EPSBN 1e-5f

// ---------------- scratch (device globals; no allocation allowed) ----------------
__device__ __half g_xh[BQ * HW * DLOI];        // fc1 output, NHWC, fp16 (33.5 MB)
__device__ float g_wfc1T[CIN * DLOI];          // [k][o], tf32-rounded
__device__ float g_c1wT[DLOI * HALF];          // [c][o]
__device__ float g_c2wT[HALF * 3 * HALF];      // [(i*3+dk)][o]
__device__ float g_c3wT[HALF * DLOI];          // [i][o]
__device__ float g_bn1s[DLOI], g_bn1t[DLOI];
__device__ float g_bn2s[HALF], g_bn2t[HALF];
__device__ float g_bn3s[HALF], g_bn3t[HALF];

__device__ __forceinline__ float to_tf32(float x) {
    uint32_t r;
    asm("cvt.rna.tf32.f32 %0, %1;" : "=r"(r) : "f"(x));
    return __uint_as_float(r);
}

// ---------------- prep: transpose weights, fold BN ----------------
__global__ void prep_kernel(const float* __restrict__ w_fc1,
                            const float* __restrict__ bn1,
                            const float* __restrict__ c1w,
                            const float* __restrict__ bn2,
                            const float* __restrict__ c2w,
                            const float* __restrict__ bn3,
                            const float* __restrict__ c3w)
{
    int t = blockIdx.x * blockDim.x + threadIdx.x;
    int stride = gridDim.x * blockDim.x;
    for (int idx = t; idx < DLOI * CIN; idx += stride) {
        int o = idx / CIN, k = idx % CIN;
        g_wfc1T[k * DLOI + o] = to_tf32(w_fc1[idx]);
    }
    for (int idx = t; idx < HALF * DLOI; idx += stride) {
        int o = idx / DLOI, c = idx % DLOI;
        g_c1wT[c * HALF + o] = c1w[idx];
    }
    for (int idx = t; idx < HALF * HALF * 3; idx += stride) {
        int o = idx / (HALF * 3), r = idx % (HALF * 3);
        g_c2wT[r * HALF + o] = c2w[idx];
    }
    for (int idx = t; idx < DLOI * HALF; idx += stride) {
        int o = idx / HALF, i = idx % HALF;
        g_c3wT[i * DLOI + o] = c3w[idx];
    }
    for (int idx = t; idx < DLOI; idx += stride) {
        float g = bn1[idx], be = bn1[DLOI + idx], mu = bn1[2*DLOI + idx], va = bn1[3*DLOI + idx];
        float s = g * rsqrtf(va + EPSBN);
        g_bn1s[idx] = s; g_bn1t[idx] = be - mu * s;
    }
    for (int idx = t; idx < HALF; idx += stride) {
        float g = bn2[idx], be = bn2[HALF + idx], mu = bn2[2*HALF + idx], va = bn2[3*HALF + idx];
        float s = g * rsqrtf(va + EPSBN);
        g_bn2s[idx] = s; g_bn2t[idx] = be - mu * s;
        float g3 = bn3[idx], be3 = bn3[HALF + idx], mu3 = bn3[2*HALF + idx], va3 = bn3[3*HALF + idx];
        float s3 = g3 * rsqrtf(va3 + EPSBN);
        g_bn3s[idx] = s3; g_bn3t[idx] = be3 - mu3 * s3;
    }
}

// ---------------- fc1 GEMM via tf32 mma.sync + cp.async double buffering ----------
#define KT 32                   // k per smem stage
#define AS_STRIDE 132           // 128 + 4 pad (words)
#define OSH 136                 // epilogue half staging stride (halves)
#define STAGE_FLOATS (2 * KT * AS_STRIDE)
#define FC1_SMEM (2 * STAGE_FLOATS * 4)

__device__ __forceinline__ void cp_async16(void* smem_ptr, const void* gmem_ptr) {
    uint32_t s = (uint32_t)__cvta_generic_to_shared(smem_ptr);
    asm volatile("cp.async.cg.shared.global [%0], [%1], 16;\n" :: "r"(s), "l"(gmem_ptr));
}

__device__ __forceinline__ void mma_tf32(float4& d, const float* a, const float* b) {
    asm volatile(
        "mma.sync.aligned.m16n8k8.row.col.f32.tf32.tf32.f32 "
        "{%0,%1,%2,%3}, {%4,%5,%6,%7}, {%8,%9}, {%0,%1,%2,%3};\n"
        : "+f"(d.x), "+f"(d.y), "+f"(d.z), "+f"(d.w)
        : "r"(__float_as_uint(a[0])), "r"(__float_as_uint(a[1])),
          "r"(__float_as_uint(a[2])), "r"(__float_as_uint(a[3])),
          "r"(__float_as_uint(b[0])), "r"(__float_as_uint(b[1])));
}

__global__ __launch_bounds__(256) void fc1_gemm_tf32(const float* __restrict__ feat,
                                                     const float* __restrict__ bfc1)
{
    extern __shared__ float sm[];

    int b  = blockIdx.y;
    int p0 = blockIdx.x * 128;
    const float* A = feat + (size_t)b * CIN * HW;
    __half* O = g_xh + (size_t)b * HW * DLOI;

    int t    = threadIdx.x;
    int w    = t >> 5;
    int lane = t & 31;
    int g    = lane >> 2;        // 0..7
    int tg   = lane & 3;         // 0..3
    int warp_m = w & 3;          // 0..3
    int warp_n = w >> 2;         // 0..1
    int m_base = warp_m * 32;
    int n_base = warp_n * 64;

    float4 acc[2][8];
#pragma unroll
    for (int mi = 0; mi < 2; mi++)
#pragma unroll
        for (int ni = 0; ni < 8; ni++) acc[mi][ni] = make_float4(0.f, 0.f, 0.f, 0.f);

    auto issue_stage = [&](int s) {
        float* As = sm + (s & 1) * STAGE_FLOATS;
        float* Bs = As + KT * AS_STRIDE;
        int k0 = s * KT;
#pragma unroll
        for (int i = 0; i < 4; i++) {
            int f  = t + 256 * i;          // 0..1023 float4 index
            int kk = f >> 5;
            int pm = (f & 31) * 4;
            cp_async16(&As[kk * AS_STRIDE + pm], &A[(size_t)(k0 + kk) * HW + p0 + pm]);
            cp_async16(&Bs[kk * AS_STRIDE + pm], &g_wfc1T[(k0 + kk) * DLOI + pm]);
        }
        asm volatile("cp.async.commit_group;\n");
    };

    issue_stage(0);

    const int NS = CIN / KT;     // 8
    for (int s = 0; s < NS; s++) {
        if (s + 1 < NS) {
            issue_stage(s + 1);
            asm volatile("cp.async.wait_group 1;\n");
        } else {
            asm volatile("cp.async.wait_group 0;\n");
        }
        __syncthreads();

        float* As = sm + (s & 1) * STAGE_FLOATS;
        float* Bs = As + KT * AS_STRIDE;

#pragma unroll
        for (int ks = 0; ks < KT / 8; ks++) {
            int kb = ks * 8;
            float afr[2][4];
#pragma unroll
            for (int mi = 0; mi < 2; mi++) {
                int r = m_base + mi * 16 + g;
                afr[mi][0] = As[(kb + tg) * AS_STRIDE + r];
                afr[mi][1] = As[(kb + tg) * AS_STRIDE + r + 8];
                afr[mi][2] = As[(kb + tg + 4) * AS_STRIDE + r];
                afr[mi][3] = As[(kb + tg + 4) * AS_STRIDE + r + 8];
            }
            float bfr[8][2];
#pragma unroll
            for (int ni = 0; ni < 8; ni++) {
                int c = n_base + ni * 8 + g;
                bfr[ni][0] = Bs[(kb + tg) * AS_STRIDE + c];
                bfr[ni][1] = Bs[(kb + tg + 4) * AS_STRIDE + c];
            }
#pragma unroll
            for (int mi = 0; mi < 2; mi++)
#pragma unroll
                for (int ni = 0; ni < 8; ni++)
                    mma_tf32(acc[mi][ni], afr[mi], bfr[ni]);
        }
        __syncthreads();
    }

    // bias per fragment column pair
    float bx[8], by[8];
#pragma unroll
    for (int ni = 0; ni < 8; ni++) {
        int c = n_base + ni * 8 + 2 * tg;
        bx[ni] = bfc1[c];
        by[ni] = bfc1[c + 1];
    }

    // epilogue: stage 64 rows at a time through smem (fp16) for coalesced NHWC stores
    __half* Osm = (__half*)sm;   // [64][OSH]
#pragma unroll
    for (int chunk = 0; chunk < 2; chunk++) {
        if ((warp_m >> 1) == chunk) {
            int rl = (warp_m & 1) * 32;
#pragma unroll
            for (int mi = 0; mi < 2; mi++) {
#pragma unroll
                for (int ni = 0; ni < 8; ni++) {
                    int row = rl + mi * 16 + g;
                    int col = n_base + ni * 8 + 2 * tg;
                    float4 d = acc[mi][ni];
                    *(__half2*)&Osm[row * OSH + col] =
                        __floats2half2_rn(d.x + bx[ni], d.y + by[ni]);
                    *(__half2*)&Osm[(row + 8) * OSH + col] =
                        __floats2half2_rn(d.z + bx[ni], d.w + by[ni]);
                }
            }
        }
        __syncthreads();
#pragma unroll
        for (int i = 0; i < 4; i++) {
            int f   = t + 256 * i;          // 0..1023; 16 x uint4 (8 halves) per row
            int row = f >> 4;
            int h0  = (f & 15) * 8;
            uint4 v = *(const uint4*)&Osm[row * OSH + h0];
            *(uint4*)&O[(size_t)(p0 + chunk * 64 + row) * DLOI + h0] = v;
        }
        __syncthreads();
    }
}

// ---------------- per-line kernel: gather + maxpool + bottleneck + fc2 + softmax ----
__global__ __launch_bounds__(128) void line_head(const float* __restrict__ lines,
                                                 const float* __restrict__ c1b,
                                                 const float* __restrict__ c2b,
                                                 const float* __restrict__ c3b,
                                                 const float* __restrict__ wfc2,
                                                 const float* __restrict__ bfc2,
                                                 float* __restrict__ out)
{
    __shared__ float sh1[DLOI * 8];     // bn1+relu, [c][p]
    __shared__ float shv[DLOI * 8];     // raw pooled (residual), [c][p]
    __shared__ float sh2[HALF * 8];
    __shared__ float sh3[HALF * 8];
    __shared__ int4   soff[NPTS0];      // half2-unit pixel offsets for 4 corners
    __shared__ float4 swt[NPTS0];       // bilinear weights
    __shared__ float shred[16];

    int n = blockIdx.x;
    int t = threadIdx.x;
    int b = n / LQ;

    // ---- precompute sample geometry (one sample per thread, t<32) ----
    if (t < NPTS0) {
        const float* ln = lines + (size_t)n * 4;
        float ax = ln[0], ay = ln[1], bx = ln[2], by = ln[3];
        float lam = (float)t * (1.0f / 31.0f);
        float px = ax * lam + bx * (1.0f - lam) - 0.5f;
        float py = ay * lam + by * (1.0f - lam) - 0.5f;
        float px0 = fminf(fmaxf(floorf(px), 0.0f), 255.0f);
        float py0 = fminf(fmaxf(floorf(py), 0.0f), 255.0f);
        float px1 = fminf(px0 + 1.0f, 255.0f);
        float py1 = fminf(py0 + 1.0f, 255.0f);
        int i0 = (int)px0, j0 = (int)py0, i1 = (int)px1, j1 = (int)py1;
        float w00 = (px1 - px) * (py1 - py);
        float w10 = (px - px0) * (py1 - py);
        float w01 = (px1 - px) * (py - py0);
        float w11 = (px - px0) * (py - py0);
        // pixel offsets in half2 units (DLOI/2 = 64 half2 per pixel)
        soff[t] = make_int4(((i0 << 8) + j0) << 6, ((i1 << 8) + j0) << 6,
                            ((i0 << 8) + j1) << 6, ((i1 << 8) + j1) << 6);
        swt[t] = make_float4(w00, w10, w01, w11);
    }
    __syncthreads();

    // ---- gather: thread = (channel pair c2, point half ph) ----
    int c2 = t & 63, ph = t >> 6;
    const __half2* X2 = (const __half2*)g_xh + (size_t)b * HW * 64 + c2;

    float2 vp[4];
#pragma unroll
    for (int pp = 0; pp < 4; pp++) {
        float2 m = make_float2(-INFINITY, -INFINITY);
#pragma unroll
        for (int kk = 0; kk < 4; kk++) {
            int k = (ph * 4 + pp) * 4 + kk;
            int4  o4 = soff[k];
            float4 w4 = swt[k];
            float2 h00 = __half22float2(__ldg(X2 + o4.x));
            float2 h10 = __half22float2(__ldg(X2 + o4.y));
            float2 h01 = __half22float2(__ldg(X2 + o4.z));
            float2 h11 = __half22float2(__ldg(X2 + o4.w));
            float vx = h00.x * w4.x + h10.x * w4.y + h01.x * w4.z + h11.x * w4.w;
            float vy = h00.y * w4.x + h10.y * w4.y + h01.y * w4.z + h11.y * w4.w;
            m.x = fmaxf(m.x, vx);
            m.y = fmaxf(m.y, vy);
        }
        vp[pp] = m;
    }

    // ---- store residual + bn1+relu to smem ([c][p], float4 along p) ----
    {
        int ca = 2 * c2, cb = 2 * c2 + 1;
        float sa = g_bn1s[ca], ta = g_bn1t[ca];
        float sb = g_bn1s[cb], tb = g_bn1t[cb];
        int base = ph * 4;
        *(float4*)&shv[ca * 8 + base] = make_float4(vp[0].x, vp[1].x, vp[2].x, vp[3].x);
        *(float4*)&shv[cb * 8 + base] = make_float4(vp[0].y, vp[1].y, vp[2].y, vp[3].y);
        *(float4*)&sh1[ca * 8 + base] = make_float4(
            fmaxf(vp[0].x * sa + ta, 0.f), fmaxf(vp[1].x * sa + ta, 0.f),
            fmaxf(vp[2].x * sa + ta, 0.f), fmaxf(vp[3].x * sa + ta, 0.f));
        *(float4*)&sh1[cb * 8 + base] = make_float4(
            fmaxf(vp[0].y * sb + tb, 0.f), fmaxf(vp[1].y * sb + tb, 0.f),
            fmaxf(vp[2].y * sb + tb, 0.f), fmaxf(vp[3].y * sb + tb, 0.f));
    }
    __syncthreads();

    int o = t & 63, half = t >> 6, pb = half * 4;

    // c1: [64,128] x [128,8] -> [64,8]; thread (o, half) does 4 p's
    float acc1[4] = {0.f, 0.f, 0.f, 0.f};
#pragma unroll 4
    for (int c = 0; c < DLOI; c++) {
        float w = g_c1wT[c * HALF + o];
        float4 h = *(const float4*)&sh1[c * 8 + pb];
        acc1[0] += w * h.x; acc1[1] += w * h.y; acc1[2] += w * h.z; acc1[3] += w * h.w;
    }
    {
        float bias = c1b[o], s2 = g_bn2s[o], t2 = g_bn2t[o];
#pragma unroll
        for (int j = 0; j < 4; j++)
            sh2[o * 8 + pb + j] = fmaxf((acc1[j] + bias) * s2 + t2, 0.0f);
    }
    __syncthreads();

    // c2: conv1d k=3 pad=1 over p, [64,64,3]
    float acc2[4] = {0.f, 0.f, 0.f, 0.f};
#pragma unroll 2
    for (int i = 0; i < HALF; i++) {
        float4 r0 = *(const float4*)&sh2[i * 8];
        float4 r1 = *(const float4*)&sh2[i * 8 + 4];
        float h[6];
        if (half == 0) { h[0] = 0.f;  h[1] = r0.x; h[2] = r0.y; h[3] = r0.z; h[4] = r0.w; h[5] = r1.x; }
        else           { h[0] = r0.w; h[1] = r1.x; h[2] = r1.y; h[3] = r1.z; h[4] = r1.w; h[5] = 0.f;  }
        float w0 = g_c2wT[(i * 3 + 0) * HALF + o];
        float w1 = g_c2wT[(i * 3 + 1) * HALF + o];
        float w2 = g_c2wT[(i * 3 + 2) * HALF + o];
#pragma unroll
        for (int j = 0; j < 4; j++)
            acc2[j] += w0 * h[j] + w1 * h[j + 1] + w2 * h[j + 2];
    }
    {
        float bias = c2b[o], s3 = g_bn3s[o], t3 = g_bn3t[o];
#pragma unroll
        for (int j = 0; j < 4; j++)
            sh3[o * 8 + pb + j] = fmaxf((acc2[j] + bias) * s3 + t3, 0.0f);
    }
    __syncthreads();

    // c3: [128,64] x [64,8] -> [128,8]; thread t = output channel, all 8 p's
    float acc3[8] = {0.f,0.f,0.f,0.f,0.f,0.f,0.f,0.f};
#pragma unroll 4
    for (int i = 0; i < HALF; i++) {
        float w = g_c3wT[i * DLOI + t];
        float4 r0 = *(const float4*)&sh3[i * 8];
        float4 r1 = *(const float4*)&sh3[i * 8 + 4];
        acc3[0] += w * r0.x; acc3[1] += w * r0.y; acc3[2] += w * r0.z; acc3[3] += w * r0.w;
        acc3[4] += w * r1.x; acc3[5] += w * r1.y; acc3[6] += w * r1.z; acc3[7] += w * r1.w;
    }
    float bias3 = c3b[t];
    float4 rv0 = *(const float4*)&shv[t * 8];
    float4 rv1 = *(const float4*)&shv[t * 8 + 4];
    float ry[8];
    ry[0] = fmaxf(rv0.x + acc3[0] + bias3, 0.f);
    ry[1] = fmaxf(rv0.y + acc3[1] + bias3, 0.f);
    ry[2] = fmaxf(rv0.z + acc3[2] + bias3, 0.f);
    ry[3] = fmaxf(rv0.w + acc3[3] + bias3, 0.f);
    ry[4] = fmaxf(rv1.x + acc3[4] + bias3, 0.f);
    ry[5] = fmaxf(rv1.y + acc3[5] + bias3, 0.f);
    ry[6] = fmaxf(rv1.z + acc3[6] + bias3, 0.f);
    ry[7] = fmaxf(rv1.w + acc3[7] + bias3, 0.f);

    // fc2 partials: flat index = t*8 + p
    float part[4];
#pragma unroll
    for (int q = 0; q < 4; q++) {
        const float* wq = wfc2 + q * (DLOI * 8) + t * 8;
        float4 w0 = *(const float4*)wq;
        float4 w1 = *(const float4*)(wq + 4);
        part[q] = ry[0] * w0.x + ry[1] * w0.y + ry[2] * w0.z + ry[3] * w0.w
                + ry[4] * w1.x + ry[5] * w1.y + ry[6] * w1.z + ry[7] * w1.w;
    }
#pragma unroll
    for (int q = 0; q < 4; q++) {
        float v = part[q];
#pragma unroll
        for (int off = 16; off; off >>= 1) v += __shfl_down_sync(0xffffffffu, v, off);
        part[q] = v;
    }
    int lane = t & 31, wid = t >> 5;
    if (lane == 0) {
#pragma unroll
        for (int q = 0; q < 4; q++) shred[wid * 4 + q] = part[q];
    }
    __syncthreads();
    if (t == 0) {
        float z[4];
#pragma unroll
        for (int q = 0; q < 4; q++)
            z[q] = shred[q] + shred[4 + q] + shred[8 + q] + shred[12 + q] + bfc2[q];
        float m = fmaxf(fmaxf(z[0], z[1]), fmaxf(z[2], z[3]));
        float e[4]; float sum = 0.f;
#pragma unroll
        for (int q = 0; q < 4; q++) { e[q] = expf(z[q] - m); sum += e[q]; }
        float inv = 1.0f / sum;
#pragma unroll
        for (int q = 0; q < 4; q++) out[(size_t)n * 4 + q] = e[q] * inv;
    }
}

// ---------------- launch ----------------
extern "C" void kernel_launch(void* const* d_in, const int* in_sizes, int n_in,
                              void* d_out, int out_size)
{
    const float* feature = (const float*)d_in[0];
    const float* lines   = (const float*)d_in[1];
    const float* w_fc1   = (const float*)d_in[2];
    const float* b_fc1   = (const float*)d_in[3];
    const float* bn1     = (const float*)d_in[4];
    const float* c1_w    = (const float*)d_in[5];
    const float* c1_b    = (const float*)d_in[6];
    const float* bn2     = (const float*)d_in[7];
    const float* c2_w    = (const float*)d_in[8];
    const float* c2_b    = (const float*)d_in[9];
    const float* bn3     = (const float*)d_in[10];
    const float* c3_w    = (const float*)d_in[11];
    const float* c3_b    = (const float*)d_in[12];
    const float* w_fc2   = (const float*)d_in[13];
    const float* b_fc2   = (const float*)d_in[14];
    float* out = (float*)d_out;

    static int smem_set = 0;
    if (!smem_set) {
        cudaFuncSetAttribute(fc1_gemm_tf32,
                             cudaFuncAttributeMaxDynamicSharedMemorySize, FC1_SMEM);
        smem_set = 1;
    }

    prep_kernel<<<64, 256>>>(w_fc1, bn1, c1_w, bn2, c2_w, bn3, c3_w);

    dim3 grid(HW / 128, BQ);
    fc1_gemm_tf32<<<grid, 256, FC1_SMEM>>>(feature, b_fc1);

    line_head<<<BQ * LQ, 128>>>(lines, c1_b, c2_b, c3_b, w_fc2, b_fc2, out);
}